// round 4
// baseline (speedup 1.0000x reference)
#include <cuda_runtime.h>

// Projection: per row i of x[N,128]:
//   sq = sum(x_i^2); s = (sq-1)/(sq+1); out_i = [(1-s)*x_i, s]  -> out[N,129]
// with (1-s) = 2/(1+sq).
//
// HBM-bound streaming. Evidence so far:
//  R1: misaligned 516B-stride stores fully merge in L2 (traffic == payload).
//  R3: raising per-thread MLP 4->16 loads took DRAM 77.5% -> 84.2%.
// R4: push MLP again: 8 rows/warp, 32 front-batched coalesced LDG.32 per
// thread (128B in flight). Scalar stride-32 stores (row stride 516B is not
// 16B aligned, vector stores illegal; scalar pattern is fully coalesced).

#define D 128
#define THREADS 256
#define WARPS (THREADS / 32)
#define ROWS_PER_WARP 8
#define ROWS_PER_BLOCK (WARPS * ROWS_PER_WARP)   // 64

__global__ void __launch_bounds__(THREADS) projection_kernel(
    const float* __restrict__ x, float* __restrict__ out, int n_rows)
{
    const int warp = threadIdx.x >> 5;
    const int lane = threadIdx.x & 31;
    const long long row0 = (long long)blockIdx.x * ROWS_PER_BLOCK
                         + (long long)warp * ROWS_PER_WARP;

    const float* __restrict__ xr = x + row0 * D + lane;

    // Front-batched, fully coalesced streaming loads: 32 x LDG.32 (128B/thread in flight)
    float v[ROWS_PER_WARP][4];
    #pragma unroll
    for (int r = 0; r < ROWS_PER_WARP; r++)
        #pragma unroll
        for (int c = 0; c < 4; c++)
            v[r][c] = __ldcs(xr + r * D + c * 32);

    float sq[ROWS_PER_WARP];
    #pragma unroll
    for (int r = 0; r < ROWS_PER_WARP; r++)
        sq[r] = v[r][0] * v[r][0] + v[r][1] * v[r][1]
              + v[r][2] * v[r][2] + v[r][3] * v[r][3];

    // Interleaved warp reductions (8 independent shuffle chains)
    #pragma unroll
    for (int off = 16; off > 0; off >>= 1)
        #pragma unroll
        for (int r = 0; r < ROWS_PER_WARP; r++)
            sq[r] += __shfl_xor_sync(0xFFFFFFFFu, sq[r], off);

    #pragma unroll
    for (int r = 0; r < ROWS_PER_WARP; r++) {
        const float inv   = 1.0f / (1.0f + sq[r]);
        const float scale = 2.0f * inv;        // = 1 - s
        const float s     = (sq[r] - 1.0f) * inv;

        float* __restrict__ orow = out + (row0 + r) * (D + 1);
        #pragma unroll
        for (int c = 0; c < 4; c++)
            orow[lane + c * 32] = scale * v[r][c];
        if (lane == 0) orow[D] = s;
    }
}

extern "C" void kernel_launch(void* const* d_in, const int* in_sizes, int n_in,
                              void* d_out, int out_size)
{
    const float* x = (const float*)d_in[0];
    float* out = (float*)d_out;
    const int n_rows = in_sizes[0] / D;                    // 1048576
    const int blocks = n_rows / ROWS_PER_BLOCK;            // exact: 16384
    projection_kernel<<<blocks, THREADS>>>(x, out, n_rows);
}

// round 7
// speedup vs baseline: 1.0018x; 1.0018x over previous
#include <cuda_runtime.h>

// Projection: per row i of x[N,128]:
//   sq = sum(x_i^2); s = (sq-1)/(sq+1); out_i = [(1-s)*x_i, s]  -> out[N,129]
// with (1-s) = 2/(1+sq).
//
// HBM-bound streaming at the mixed r/w wall (~6.7 TB/s measured R3/R4).
// R5: R3 shape (4 rows/warp) with overhead trimmed:
//  - float4 streaming loads (input rows 512B-aligned): 4x fewer LDG + IMADs
//  - single partially-active STG for the 4 per-row tail scalars `s`
//    (every lane holds all sq[r] after the interleaved reductions)
//  - scalar stride-32 data stores (516B row stride; L2 merges fully, R1).

#define D 128
#define THREADS 256
#define WARPS (THREADS / 32)
#define ROWS_PER_WARP 4
#define ROWS_PER_BLOCK (WARPS * ROWS_PER_WARP)   // 32

__global__ void __launch_bounds__(THREADS) projection_kernel(
    const float4* __restrict__ x4, float* __restrict__ out, int n_rows)
{
    const int warp = threadIdx.x >> 5;
    const int lane = threadIdx.x & 31;
    const long long row0 = (long long)blockIdx.x * ROWS_PER_BLOCK
                         + (long long)warp * ROWS_PER_WARP;

    // Row r, lane t covers cols [4t, 4t+4): one LDG.128 per row per thread.
    const float4* __restrict__ xr = x4 + row0 * (D / 4) + lane;

    float4 v[ROWS_PER_WARP];
    #pragma unroll
    for (int r = 0; r < ROWS_PER_WARP; r++)
        v[r] = __ldcs(xr + r * (D / 4));

    float sq[ROWS_PER_WARP];
    #pragma unroll
    for (int r = 0; r < ROWS_PER_WARP; r++)
        sq[r] = v[r].x * v[r].x + v[r].y * v[r].y
              + v[r].z * v[r].z + v[r].w * v[r].w;

    // Interleaved warp reductions; afterwards every lane holds all sq[r]
    #pragma unroll
    for (int off = 16; off > 0; off >>= 1)
        #pragma unroll
        for (int r = 0; r < ROWS_PER_WARP; r++)
            sq[r] += __shfl_xor_sync(0xFFFFFFFFu, sq[r], off);

    #pragma unroll
    for (int r = 0; r < ROWS_PER_WARP; r++) {
        const float inv   = 1.0f / (1.0f + sq[r]);
        const float scale = 2.0f * inv;        // = 1 - s

        float* __restrict__ orow = out + (row0 + r) * (D + 1) + 4 * lane;
        orow[0] = scale * v[r].x;
        orow[1] = scale * v[r].y;
        orow[2] = scale * v[r].z;
        orow[3] = scale * v[r].w;
    }

    // Tail scalars: lane r stores s for row (row0 + r) — one STG, 4 active lanes.
    if (lane < ROWS_PER_WARP) {
        const float sql = sq[lane];
        out[(row0 + lane) * (D + 1) + D] = (sql - 1.0f) / (1.0f + sql);
    }
}

extern "C" void kernel_launch(void* const* d_in, const int* in_sizes, int n_in,
                              void* d_out, int out_size)
{
    const float4* x4 = (const float4*)d_in[0];
    float* out = (float*)d_out;
    const int n_rows = in_sizes[0] / D;                    // 1048576
    const int blocks = n_rows / ROWS_PER_BLOCK;            // exact: 32768
    projection_kernel<<<blocks, THREADS>>>(x4, out, n_rows);
}